// round 17
// baseline (speedup 1.0000x reference)
#include <cuda_runtime.h>
#include <cstdint>

// CovarianceLayer: x [64, 4, 8192, 16] fp32 -> cov [64, 4, 16, 16] fp32
// Grid 1024 = 256 (b,c) x 4 T-chunks (2048 rows each) to fix CTA->SM load
// imbalance (256 CTAs on 296 occ-2 slots left 40 SMs half idle). Main loop is
// identical to the 41.5us kernel: warp-autonomous smem double-buffer staging,
// branchless lane-parity triangle split, 40 packed-f32x2 accumulators,
// L2 prefetch 4 stages ahead. Cross-CTA combine is DETERMINISTIC: each chunk
// writes partials to its own slot; a ticket counter elects the last CTA per bc
// to sum the 4 slots in fixed order, finalize, and reset the counter.

#define T_DIM    8192
#define M_DIM    16
#define NTHREADS 256
#define NU       40        // f32x2 units per parity half: 36 triangle + 4 column-sum
#define SPLIT    4
#define NSTAGES  16        // 2048 rows / (8 warps * 16 rows)
#define PITCH    80        // bytes per row in smem
#define STAGE_B  (16 * PITCH)
#define PF_DIST  4         // L2 prefetch lead, in stages

typedef unsigned long long ull;

__device__ float g_part[256][SPLIT][4 * NU];
__device__ int   g_count[256];          // zero-initialized; reset each call

__device__ __forceinline__ void fma2(ull& d, ull a, ull b) {
    asm("fma.rn.f32x2 %0, %1, %2, %0;" : "+l"(d) : "l"(a), "l"(b));
}
__device__ __forceinline__ void add2(ull& d, ull a) {
    asm("add.rn.f32x2 %0, %1, %0;" : "+l"(d) : "l"(a));
}
__device__ __forceinline__ float2 u2f(ull u) {
    float2 f; asm("mov.b64 {%0,%1}, %2;" : "=f"(f.x), "=f"(f.y) : "l"(u)); return f;
}
__device__ __forceinline__ ull f2u(float lo, float hi) {
    ull u; asm("mov.b64 %0, {%1,%2};" : "=l"(u) : "f"(lo), "f"(hi)); return u;
}
__device__ __forceinline__ void pf_l2(const void* p) {
    asm volatile("prefetch.global.L2 [%0];" :: "l"(p));
}
__device__ __forceinline__ void sts16(uint32_t addr, ulonglong2 v) {
    asm volatile("st.shared.v2.u64 [%0], {%1,%2};" :: "r"(addr), "l"(v.x), "l"(v.y) : "memory");
}
__device__ __forceinline__ void lds16(uint32_t addr, ull& a, ull& b) {
    asm volatile("ld.shared.v2.u64 {%0,%1}, [%2];" : "=l"(a), "=l"(b) : "r"(addr));
}

__host__ __device__ __forceinline__ int unit_base(int a) { return 8 * a - a * (a - 1) / 2; }

// Branchless: `odd` is per-lane data, lowered to SEL/FSEL — no divergence.
__device__ __forceinline__ void accum_row(ull acc[NU], const ull v[8], bool odd) {
    #pragma unroll
    for (int a = 0; a < 8; a++) {            // m = 2a + parity
        float2 c = u2f(v[a]);
        const float vm = odd ? c.y : c.x;    // FSEL
        const ull bm = f2u(vm, vm);
        #pragma unroll
        for (int j = a; j < 8; j++)
            fma2(acc[unit_base(a) + j - a], bm, v[j]);
    }
    #pragma unroll
    for (int j = 0; j < 4; j++)
        add2(acc[36 + j], odd ? v[4 + j] : v[j]);
}

__global__ void __launch_bounds__(NTHREADS, 2)
cov_kernel(const float* __restrict__ x, float* __restrict__ out)
{
    __shared__ __align__(16) unsigned char sbuf[8 * 2 * STAGE_B];
    __shared__ float red[8][4 * NU];
    __shared__ float tot[4 * NU];
    __shared__ int   is_last;

    const int bc    = blockIdx.x >> 2;
    const int chunk = blockIdx.x & 3;
    const int tid = threadIdx.x;
    const int wid = tid >> 5;
    const int lid = tid & 31;
    const bool odd = (lid & 1);
    const int p   = lid >> 1;

    // gmem: this chunk covers rows [chunk*2048, chunk*2048+2048)
    const char* gw = reinterpret_cast<const char*>(x + (size_t)bc * T_DIM * M_DIM)
                   + (size_t)chunk * 2048 * 64
                   + (size_t)wid * 1024;
    const size_t off0 = (size_t)lid * 16;
    const size_t off1 = 512 + (size_t)lid * 16;

    const uint32_t wbuf = (uint32_t)__cvta_generic_to_shared(sbuf)
                        + (uint32_t)wid * (2 * STAGE_B);
    const uint32_t stsA = (uint32_t)(((lid >> 2)    ) * PITCH + (lid & 3) * 16);
    const uint32_t stsB = (uint32_t)(((lid >> 2) + 8) * PITCH + (lid & 3) * 16);
    const uint32_t ldsb = (uint32_t)(p * PITCH);

    ull acc[NU];
    #pragma unroll
    for (int i = 0; i < NU; i++) acc[i] = 0ULL;

    // ---- prologue ----
    ulonglong2 A0 = *reinterpret_cast<const ulonglong2*>(gw + off0);
    ulonglong2 A1 = *reinterpret_cast<const ulonglong2*>(gw + off1);
    sts16(wbuf + stsA, A0);
    sts16(wbuf + stsB, A1);
    A0 = *reinterpret_cast<const ulonglong2*>(gw + 8192 + off0);
    A1 = *reinterpret_cast<const ulonglong2*>(gw + 8192 + off1);
    #pragma unroll
    for (int s = 2; s < PF_DIST + 2; s++)
        pf_l2(gw + (size_t)s * 8192 + (lid & 7) * 128);
    __syncwarp();

    // ---- main loop: 16 stages, warp-autonomous ----
    #pragma unroll 1
    for (int s = 0; s < NSTAGES; s++) {
        const uint32_t rb = wbuf + (uint32_t)(s & 1) * STAGE_B;
        const uint32_t wb = wbuf + (uint32_t)((s + 1) & 1) * STAGE_B;

        ull v[8];
        lds16(rb + ldsb +  0, v[0], v[1]);
        lds16(rb + ldsb + 16, v[2], v[3]);
        lds16(rb + ldsb + 32, v[4], v[5]);
        lds16(rb + ldsb + 48, v[6], v[7]);

        sts16(wb + stsA, A0);
        sts16(wb + stsB, A1);

        if (s + 2 < NSTAGES) {
            A0 = *reinterpret_cast<const ulonglong2*>(gw + (size_t)(s + 2) * 8192 + off0);
            A1 = *reinterpret_cast<const ulonglong2*>(gw + (size_t)(s + 2) * 8192 + off1);
        }
        if (s + PF_DIST + 2 < NSTAGES)
            pf_l2(gw + (size_t)(s + PF_DIST + 2) * 8192 + (lid & 7) * 128);

        accum_row(acc, v, odd);
        __syncwarp();
    }

    // ---- intra-warp reduce (parity-preserving xor strides 2,4,8,16) ----
    #pragma unroll 1
    for (int i = 0; i < NU; i++) {
        float2 f = u2f(acc[i]);
        #pragma unroll
        for (int o = 2; o <= 16; o <<= 1) {
            f.x += __shfl_xor_sync(0xFFFFFFFFu, f.x, o);
            f.y += __shfl_xor_sync(0xFFFFFFFFu, f.y, o);
        }
        if (lid < 2) {
            red[wid][lid * (2 * NU) + 2 * i]     = f.x;
            red[wid][lid * (2 * NU) + 2 * i + 1] = f.y;
        }
    }
    __syncthreads();

    if (tid < 4 * NU) {
        float s = 0.0f;
        #pragma unroll
        for (int w = 0; w < 8; w++) s += red[w][tid];
        g_part[bc][chunk][tid] = s;      // this chunk's partials, own slot
        __threadfence();
    }
    __syncthreads();

    // ---- ticket: last chunk-CTA of this bc finalizes ----
    if (tid == 0) {
        const int t = atomicAdd(&g_count[bc], 1);
        __threadfence();
        is_last = (t == SPLIT - 1);
    }
    __syncthreads();
    if (!is_last) return;

    if (tid < 4 * NU) {                  // deterministic fixed-order sum
        float s = 0.0f;
        #pragma unroll
        for (int c = 0; c < SPLIT; c++) s += g_part[bc][c][tid];
        tot[tid] = s;
    }
    __syncthreads();

    // ---- finalize: thread (m,n) ----
    {
        const int m  = tid >> 4;
        const int n  = tid & 15;
        const int mm = (m < n) ? m : n;
        const int nn = (m < n) ? n : m;
        const int H  = mm & 1;
        const int a  = mm >> 1;
        const float S = tot[H * 80 + (unit_base(a) + (nn >> 1) - a) * 2 + (nn & 1)];

        const int jm = m >> 1, jn = n >> 1;
        const float sm = tot[((jm >= 4) ? 80 : 0) + (36 + (jm & 3)) * 2 + (m & 1)];
        const float sn = tot[((jn >= 4) ? 80 : 0) + (36 + (jn & 3)) * 2 + (n & 1)];

        const float inv_T  = 1.0f / (float)T_DIM;
        const float inv_T1 = 1.0f / (float)(T_DIM - 1);
        out[(size_t)bc * 256 + tid] = (S - sm * sn * inv_T) * inv_T1;
    }

    if (tid == 0) g_count[bc] = 0;       // reset for next graph replay
}

extern "C" void kernel_launch(void* const* d_in, const int* in_sizes, int n_in,
                              void* d_out, int out_size)
{
    const float* x = (const float*)d_in[0];
    float* out = (float*)d_out;
    cov_kernel<<<256 * SPLIT, NTHREADS>>>(x, out);
}